// round 1
// baseline (speedup 1.0000x reference)
#include <cuda_runtime.h>

namespace {

constexpr int Bc = 1024;
constexpr int Tc = 1024;
constexpr int Dc = 256;
constexpr int Mc = 10;
constexpr int COPY_BLOCKS = 4096;

__global__ __launch_bounds__(256, 2) void bjrnn_fused(
    const float* __restrict__ x,
    const float* __restrict__ hist,
    const float* __restrict__ Wi, const float* __restrict__ bi,
    const float* __restrict__ Wk, const float* __restrict__ bk,
    const float* __restrict__ Wv, const float* __restrict__ bv,
    const float* __restrict__ Wb, const float* __restrict__ bb,
    const int*  __restrict__ jumps,
    const int*  __restrict__ curp,
    float* __restrict__ oh,      // [B, D]
    float* __restrict__ oy,      // [B, D]
    float* __restrict__ ohist)   // [B, T, D]
{
    const int cur = __ldg(curp);

    // ---------------- copy role: bulk history copy, skipping t == cur ----
    if (blockIdx.x >= Bc) {
        const float4* __restrict__ src = reinterpret_cast<const float4*>(hist);
        float4*       __restrict__ dst = reinterpret_cast<float4*>(ohist);
        const long long total  = (long long)Bc * Tc * (Dc / 4);   // 64M float4
        const long long stride = (long long)(gridDim.x - Bc) * blockDim.x;
        long long i = (long long)(blockIdx.x - Bc) * blockDim.x + threadIdx.x;
        // row (b,t) = 64 consecutive float4s; t = (i>>6) & (T-1)
        for (; i + 3 * stride < total; i += 4 * stride) {
            const long long i0 = i, i1 = i + stride, i2 = i + 2 * stride, i3 = i + 3 * stride;
            float4 v0 = src[i0];
            float4 v1 = src[i1];
            float4 v2 = src[i2];
            float4 v3 = src[i3];
            if ((int)((i0 >> 6) & (Tc - 1)) != cur) dst[i0] = v0;
            if ((int)((i1 >> 6) & (Tc - 1)) != cur) dst[i1] = v1;
            if ((int)((i2 >> 6) & (Tc - 1)) != cur) dst[i2] = v2;
            if ((int)((i3 >> 6) & (Tc - 1)) != cur) dst[i3] = v3;
        }
        for (; i < total; i += stride) {
            if ((int)((i >> 6) & (Tc - 1)) != cur) dst[i] = src[i];
        }
        return;
    }

    // ---------------- compute role: one block per batch row ---------------
    __shared__ float xs[Dc];
    __shared__ float Hs[Mc][Dc];
    __shared__ float hsm[Dc];
    __shared__ float red[8][Mc];
    __shared__ float ssm[Mc];

    const int b = blockIdx.x;
    const int j = threadIdx.x;      // output column owned by this thread
    const int lane = j & 31;
    const int warp = j >> 5;

    xs[j] = x[b * Dc + j];
    #pragma unroll
    for (int m = 0; m < Mc; ++m) {
        int idx = cur - __ldg(&jumps[m]);
        idx = idx < 0 ? 0 : idx;
        Hs[m][j] = hist[((long long)b * Tc + idx) * Dc + j];
    }
    __syncthreads();

    // q[j], K[m][j], V[m][j] accumulated in registers; W columns streamed from L2.
    float q = bi[j];
    float Ka[Mc], Va[Mc];
    {
        const float kb = bk[j], vb = bv[j];
        #pragma unroll
        for (int m = 0; m < Mc; ++m) { Ka[m] = kb; Va[m] = vb; }
    }

    #pragma unroll 1
    for (int d0 = 0; d0 < Dc; d0 += 4) {
        const float4 xv = *reinterpret_cast<const float4*>(&xs[d0]);
        float4 hv[Mc];
        #pragma unroll
        for (int m = 0; m < Mc; ++m)
            hv[m] = *reinterpret_cast<const float4*>(&Hs[m][d0]);
        #pragma unroll
        for (int dd = 0; dd < 4; ++dd) {
            const int d  = d0 + dd;
            const float wi = Wi[d * Dc + j];
            const float wk = Wk[d * Dc + j];
            const float wv = Wv[d * Dc + j];
            const float xd = (&xv.x)[dd];
            q = fmaf(xd, wi, q);
            #pragma unroll
            for (int m = 0; m < Mc; ++m) {
                const float hd = (&hv[m].x)[dd];
                Ka[m] = fmaf(hd, wk, Ka[m]);
                Va[m] = fmaf(hd, wv, Va[m]);
            }
        }
    }

    // scores[m] = sum_j q[j]*K[m][j]  — deterministic tree reduction
    #pragma unroll
    for (int m = 0; m < Mc; ++m) {
        float v = q * Ka[m];
        #pragma unroll
        for (int o = 16; o; o >>= 1) v += __shfl_xor_sync(0xFFFFFFFFu, v, o);
        if (lane == 0) red[warp][m] = v;
    }
    __syncthreads();
    if (j < Mc) {
        float s = 0.f;
        #pragma unroll
        for (int w = 0; w < 8; ++w) s += red[w][j];
        ssm[j] = s * (1.0f / 16.0f);   // / sqrt(D), D = 256
    }
    __syncthreads();

    // softmax over M=10 (computed redundantly per thread — trivial)
    float sc[Mc];
    #pragma unroll
    for (int m = 0; m < Mc; ++m) sc[m] = ssm[m];
    float mx = sc[0];
    #pragma unroll
    for (int m = 1; m < Mc; ++m) mx = fmaxf(mx, sc[m]);
    float esum = 0.f;
    #pragma unroll
    for (int m = 0; m < Mc; ++m) { sc[m] = __expf(sc[m] - mx); esum += sc[m]; }
    const float inv = 1.0f / esum;

    float rs = 0.f;
    #pragma unroll
    for (int m = 0; m < Mc; ++m) rs = fmaf(sc[m] * inv, Va[m], rs);

    const float h = 1.0f / (1.0f + __expf(-(q + rs)));
    hsm[j] = h;
    oh[b * Dc + j] = h;
    ohist[((long long)b * Tc + cur) * Dc + j] = h;   // copy blocks skip this slice
    __syncthreads();

    // y = sigmoid(h @ W_bl + b_bl + h)
    float acc = bb[j] + h;
    #pragma unroll 1
    for (int d0 = 0; d0 < Dc; d0 += 4) {
        const float4 hv = *reinterpret_cast<const float4*>(&hsm[d0]);
        acc = fmaf(hv.x, Wb[(d0 + 0) * Dc + j], acc);
        acc = fmaf(hv.y, Wb[(d0 + 1) * Dc + j], acc);
        acc = fmaf(hv.z, Wb[(d0 + 2) * Dc + j], acc);
        acc = fmaf(hv.w, Wb[(d0 + 3) * Dc + j], acc);
    }
    oy[b * Dc + j] = 1.0f / (1.0f + __expf(-acc));
}

} // namespace

extern "C" void kernel_launch(void* const* d_in, const int* in_sizes, int n_in,
                              void* d_out, int out_size)
{
    // metadata order: x, h_history, W_in_w, W_in_b, W_k_w, W_k_b,
    //                 W_v_w, W_v_b, W_bl_w, W_bl_b, backward_jumps, current_index
    const float* x    = (const float*)d_in[0];
    const float* hist = (const float*)d_in[1];
    const float* Wi   = (const float*)d_in[2];
    const float* bi   = (const float*)d_in[3];
    const float* Wk   = (const float*)d_in[4];
    const float* bk   = (const float*)d_in[5];
    const float* Wv   = (const float*)d_in[6];
    const float* bv   = (const float*)d_in[7];
    const float* Wb   = (const float*)d_in[8];
    const float* bb   = (const float*)d_in[9];
    const int*   jp   = (const int*)d_in[10];
    const int*   cur  = (const int*)d_in[11];

    float* out   = (float*)d_out;
    float* oh    = out;                    // h:  [B, D]
    float* oy    = out + Bc * Dc;          // y:  [B, D]
    float* ohist = out + 2 * Bc * Dc;      // new_history: [B, T, D]

    (void)in_sizes; (void)n_in; (void)out_size;

    bjrnn_fused<<<Bc + COPY_BLOCKS, 256>>>(
        x, hist, Wi, bi, Wk, bk, Wv, bv, Wb, bb, jp, cur, oh, oy, ohist);
}

// round 2
// speedup vs baseline: 1.2330x; 1.2330x over previous
#include <cuda_runtime.h>

namespace {

constexpr int Bc = 1024;
constexpr int Tc = 1024;
constexpr int Dc = 256;
constexpr int Mc = 10;
constexpr int ROWS = 2;
constexpr int CBLK = Bc / ROWS;   // 512 compute blocks
constexpr int GRID = 592;         // 4 blocks/SM * 148 SMs — one resident wave

__device__ __forceinline__ float sigf(float v) {
    return 1.0f / (1.0f + __expf(-v));
}

__global__ __launch_bounds__(256, 4) void bjrnn_fused(
    const float* __restrict__ x,
    const float* __restrict__ hist,
    const float* __restrict__ Wi, const float* __restrict__ bi,
    const float* __restrict__ Wk, const float* __restrict__ bk,
    const float* __restrict__ Wv, const float* __restrict__ bv,
    const float* __restrict__ Wb, const float* __restrict__ bb,
    const int*  __restrict__ jumps,
    const int*  __restrict__ curp,
    float* __restrict__ oh,      // [B, D]
    float* __restrict__ oy,      // [B, D]
    float* __restrict__ ohist)   // [B, T, D]
{
    const int cur = __ldg(curp);
    const int j = threadIdx.x;

    // ================= compute phase: blocks [0, 512), 2 batch rows each ===
    if (blockIdx.x < CBLK) {
        __shared__ float xs [ROWS][Dc];
        __shared__ float Hs [ROWS][Mc][Dc];
        __shared__ float qs [ROWS][Dc];
        __shared__ float gs [ROWS][Dc];
        __shared__ float hsh[ROWS][Dc];
        __shared__ float red[8][2 * Mc];
        __shared__ float scs[ROWS][Mc];
        __shared__ float attn[ROWS][Mc];

        const int b0   = blockIdx.x * ROWS;
        const int lane = j & 31;
        const int warp = j >> 5;

        #pragma unroll
        for (int r = 0; r < ROWS; ++r) xs[r][j] = x[(b0 + r) * Dc + j];
        #pragma unroll
        for (int m = 0; m < Mc; ++m) {
            int idx = cur - __ldg(&jumps[m]);
            idx = idx < 0 ? 0 : idx;
            #pragma unroll
            for (int r = 0; r < ROWS; ++r)
                Hs[r][m][j] = hist[((long long)(b0 + r) * Tc + idx) * Dc + j];
        }
        __syncthreads();

        // --- q = x @ Wi + bi  (coalesced column GEMV, 2 rows share each w)
        float qa0 = bi[j], qa1 = qa0;
        #pragma unroll 8
        for (int d = 0; d < Dc; ++d) {
            const float w = Wi[d * Dc + j];
            qa0 = fmaf(xs[0][d], w, qa0);
            qa1 = fmaf(xs[1][d], w, qa1);
        }
        qs[0][j] = qa0; qs[1][j] = qa1;
        __syncthreads();

        // --- p[d=j] = sum_k Wk[j,k] * q[k]   (thread j reads row j, contiguous)
        float p0 = 0.f, p1 = 0.f;
        {
            const float4* __restrict__ wrow =
                reinterpret_cast<const float4*>(Wk + j * Dc);
            #pragma unroll 8
            for (int k4 = 0; k4 < Dc / 4; ++k4) {
                const float4 w = __ldg(wrow + k4);
                const int k = k4 * 4;
                p0 = fmaf(w.x, qs[0][k],     p0);
                p0 = fmaf(w.y, qs[0][k + 1], p0);
                p0 = fmaf(w.z, qs[0][k + 2], p0);
                p0 = fmaf(w.w, qs[0][k + 3], p0);
                p1 = fmaf(w.x, qs[1][k],     p1);
                p1 = fmaf(w.y, qs[1][k + 1], p1);
                p1 = fmaf(w.z, qs[1][k + 2], p1);
                p1 = fmaf(w.w, qs[1][k + 3], p1);
            }
        }

        // --- scores[m] = sum_d H[m,d] * p[d]   (q.bk term is softmax-invariant)
        #pragma unroll
        for (int m = 0; m < Mc; ++m) {
            float v0 = Hs[0][m][j] * p0;
            float v1 = Hs[1][m][j] * p1;
            #pragma unroll
            for (int o = 16; o; o >>= 1) {
                v0 += __shfl_xor_sync(0xFFFFFFFFu, v0, o);
                v1 += __shfl_xor_sync(0xFFFFFFFFu, v1, o);
            }
            if (lane == 0) { red[warp][m] = v0; red[warp][Mc + m] = v1; }
        }
        __syncthreads();
        if (j < 2 * Mc) {
            float s = 0.f;
            #pragma unroll
            for (int w = 0; w < 8; ++w) s += red[w][j];
            scs[j / Mc][j % Mc] = s * (1.0f / 16.0f);   // / sqrt(256)
        }
        __syncthreads();
        if (j < ROWS) {   // per-row softmax over 10 values
            float mx = scs[j][0];
            #pragma unroll
            for (int m = 1; m < Mc; ++m) mx = fmaxf(mx, scs[j][m]);
            float e[Mc], es = 0.f;
            #pragma unroll
            for (int m = 0; m < Mc; ++m) { e[m] = __expf(scs[j][m] - mx); es += e[m]; }
            const float inv = 1.0f / es;
            #pragma unroll
            for (int m = 0; m < Mc; ++m) attn[j][m] = e[m] * inv;
        }
        __syncthreads();

        // --- g[d] = sum_m attn[m] * H[m,d]
        #pragma unroll
        for (int r = 0; r < ROWS; ++r) {
            float g = 0.f;
            #pragma unroll
            for (int m = 0; m < Mc; ++m) g = fmaf(attn[r][m], Hs[r][m][j], g);
            gs[r][j] = g;
        }
        __syncthreads();

        // --- rs = g @ Wv + bv ;  h = sigmoid(q + rs)
        float ra0 = bv[j], ra1 = ra0;
        #pragma unroll 8
        for (int d = 0; d < Dc; ++d) {
            const float w = Wv[d * Dc + j];
            ra0 = fmaf(gs[0][d], w, ra0);
            ra1 = fmaf(gs[1][d], w, ra1);
        }
        const float h0 = sigf(qa0 + ra0);
        const float h1 = sigf(qa1 + ra1);
        hsh[0][j] = h0; hsh[1][j] = h1;
        oh[(b0 + 0) * Dc + j] = h0;
        oh[(b0 + 1) * Dc + j] = h1;
        ohist[((long long)(b0 + 0) * Tc + cur) * Dc + j] = h0;
        ohist[((long long)(b0 + 1) * Tc + cur) * Dc + j] = h1;
        __syncthreads();

        // --- y = sigmoid(h @ Wb + bb + h)
        float ya0 = bb[j] + h0, ya1 = bb[j] + h1;
        #pragma unroll 8
        for (int d = 0; d < Dc; ++d) {
            const float w = Wb[d * Dc + j];
            ya0 = fmaf(hsh[0][d], w, ya0);
            ya1 = fmaf(hsh[1][d], w, ya1);
        }
        oy[(b0 + 0) * Dc + j] = sigf(ya0);
        oy[(b0 + 1) * Dc + j] = sigf(ya1);
    }

    // ================= copy phase: ALL blocks grid-stride the history =======
    {
        const float4* __restrict__ src = reinterpret_cast<const float4*>(hist);
        float4*       __restrict__ dst = reinterpret_cast<float4*>(ohist);
        const long long total  = (long long)Bc * Tc * (Dc / 4);   // 64M float4
        const long long stride = (long long)GRID * 256;
        long long i = (long long)blockIdx.x * 256 + j;
        for (; i + 3 * stride < total; i += 4 * stride) {
            const long long i0 = i, i1 = i + stride, i2 = i + 2 * stride,
                            i3 = i + 3 * stride;
            const float4 v0 = __ldcs(src + i0);
            const float4 v1 = __ldcs(src + i1);
            const float4 v2 = __ldcs(src + i2);
            const float4 v3 = __ldcs(src + i3);
            if ((int)((i0 >> 6) & (Tc - 1)) != cur) __stcs(dst + i0, v0);
            if ((int)((i1 >> 6) & (Tc - 1)) != cur) __stcs(dst + i1, v1);
            if ((int)((i2 >> 6) & (Tc - 1)) != cur) __stcs(dst + i2, v2);
            if ((int)((i3 >> 6) & (Tc - 1)) != cur) __stcs(dst + i3, v3);
        }
        for (; i < total; i += stride) {
            const float4 v = __ldcs(src + i);
            if ((int)((i >> 6) & (Tc - 1)) != cur) __stcs(dst + i, v);
        }
    }
}

} // namespace

extern "C" void kernel_launch(void* const* d_in, const int* in_sizes, int n_in,
                              void* d_out, int out_size)
{
    const float* x    = (const float*)d_in[0];
    const float* hist = (const float*)d_in[1];
    const float* Wi   = (const float*)d_in[2];
    const float* bi   = (const float*)d_in[3];
    const float* Wk   = (const float*)d_in[4];
    const float* bk   = (const float*)d_in[5];
    const float* Wv   = (const float*)d_in[6];
    const float* bv   = (const float*)d_in[7];
    const float* Wb   = (const float*)d_in[8];
    const float* bb   = (const float*)d_in[9];
    const int*   jp   = (const int*)d_in[10];
    const int*   cur  = (const int*)d_in[11];

    float* out   = (float*)d_out;
    float* oh    = out;                    // h:  [B, D]
    float* oy    = out + Bc * Dc;          // y:  [B, D]
    float* ohist = out + 2 * Bc * Dc;      // new_history: [B, T, D]

    (void)in_sizes; (void)n_in; (void)out_size;

    bjrnn_fused<<<GRID, 256>>>(
        x, hist, Wi, bi, Wk, bk, Wv, bv, Wb, bb, jp, cur, oh, oy, ohist);
}

// round 3
// speedup vs baseline: 1.2414x; 1.0069x over previous
#include <cuda_runtime.h>

namespace {

constexpr int Bc = 1024;
constexpr int Tc = 1024;
constexpr int Dc = 256;
constexpr int Mc = 10;
constexpr int ROWS = 2;
constexpr int CBLK = Bc / ROWS;   // 512 compute blocks
constexpr int GRID = 592;         // 4 blocks/SM * 148 SMs — one resident wave

__device__ __forceinline__ float sigf(float v) {
    return 1.0f / (1.0f + __expf(-v));
}

__global__ __launch_bounds__(256, 4) void bjrnn_fused(
    const float* __restrict__ x,
    const float* __restrict__ hist,
    const float* __restrict__ Wi, const float* __restrict__ bi,
    const float* __restrict__ Wk, const float* __restrict__ bk,
    const float* __restrict__ Wv, const float* __restrict__ bv,
    const float* __restrict__ Wb, const float* __restrict__ bb,
    const int*  __restrict__ jumps,
    const int*  __restrict__ curp,
    float* __restrict__ oh,      // [B, D]
    float* __restrict__ oy,      // [B, D]
    float* __restrict__ ohist)   // [B, T, D]
{
    const int cur = __ldg(curp);
    const int j = threadIdx.x;

    // ================= compute phase: blocks [0, 512), 2 batch rows each ===
    if (blockIdx.x < CBLK) {
        __shared__ float xs [ROWS][Dc];
        __shared__ float Hs [ROWS][Mc][Dc];
        __shared__ float qs [ROWS][Dc];
        __shared__ float gs [ROWS][Dc];
        __shared__ float hsh[ROWS][Dc];
        __shared__ float red[8][2 * Mc];
        __shared__ float scs[ROWS][Mc];
        __shared__ float attn[ROWS][Mc];

        const int b0   = blockIdx.x * ROWS;
        const int lane = j & 31;
        const int warp = j >> 5;

        #pragma unroll
        for (int r = 0; r < ROWS; ++r) xs[r][j] = x[(b0 + r) * Dc + j];
        #pragma unroll
        for (int m = 0; m < Mc; ++m) {
            int idx = cur - __ldg(&jumps[m]);
            idx = idx < 0 ? 0 : idx;
            #pragma unroll
            for (int r = 0; r < ROWS; ++r)
                Hs[r][m][j] = hist[((long long)(b0 + r) * Tc + idx) * Dc + j];
        }
        __syncthreads();

        // --- q = x @ Wi + bi  (coalesced column GEMV, 2 rows share each w)
        float qa0 = bi[j], qa1 = qa0;
        #pragma unroll 8
        for (int d = 0; d < Dc; ++d) {
            const float w = Wi[d * Dc + j];
            qa0 = fmaf(xs[0][d], w, qa0);
            qa1 = fmaf(xs[1][d], w, qa1);
        }
        qs[0][j] = qa0; qs[1][j] = qa1;
        __syncthreads();

        // --- p[d=j] = sum_k Wk[j,k] * q[k]   (thread j reads row j, contiguous)
        float p0 = 0.f, p1 = 0.f;
        {
            const float4* __restrict__ wrow =
                reinterpret_cast<const float4*>(Wk + j * Dc);
            #pragma unroll 8
            for (int k4 = 0; k4 < Dc / 4; ++k4) {
                const float4 w = __ldg(wrow + k4);
                const int k = k4 * 4;
                p0 = fmaf(w.x, qs[0][k],     p0);
                p0 = fmaf(w.y, qs[0][k + 1], p0);
                p0 = fmaf(w.z, qs[0][k + 2], p0);
                p0 = fmaf(w.w, qs[0][k + 3], p0);
                p1 = fmaf(w.x, qs[1][k],     p1);
                p1 = fmaf(w.y, qs[1][k + 1], p1);
                p1 = fmaf(w.z, qs[1][k + 2], p1);
                p1 = fmaf(w.w, qs[1][k + 3], p1);
            }
        }

        // --- scores[m] = sum_d H[m,d] * p[d]   (q.bk term is softmax-invariant)
        #pragma unroll
        for (int m = 0; m < Mc; ++m) {
            float v0 = Hs[0][m][j] * p0;
            float v1 = Hs[1][m][j] * p1;
            #pragma unroll
            for (int o = 16; o; o >>= 1) {
                v0 += __shfl_xor_sync(0xFFFFFFFFu, v0, o);
                v1 += __shfl_xor_sync(0xFFFFFFFFu, v1, o);
            }
            if (lane == 0) { red[warp][m] = v0; red[warp][Mc + m] = v1; }
        }
        __syncthreads();
        if (j < 2 * Mc) {
            float s = 0.f;
            #pragma unroll
            for (int w = 0; w < 8; ++w) s += red[w][j];
            scs[j / Mc][j % Mc] = s * (1.0f / 16.0f);   // / sqrt(256)
        }
        __syncthreads();
        if (j < ROWS) {   // per-row softmax over 10 values
            float mx = scs[j][0];
            #pragma unroll
            for (int m = 1; m < Mc; ++m) mx = fmaxf(mx, scs[j][m]);
            float e[Mc], es = 0.f;
            #pragma unroll
            for (int m = 0; m < Mc; ++m) { e[m] = __expf(scs[j][m] - mx); es += e[m]; }
            const float inv = 1.0f / es;
            #pragma unroll
            for (int m = 0; m < Mc; ++m) attn[j][m] = e[m] * inv;
        }
        __syncthreads();

        // --- g[d] = sum_m attn[m] * H[m,d]
        #pragma unroll
        for (int r = 0; r < ROWS; ++r) {
            float g = 0.f;
            #pragma unroll
            for (int m = 0; m < Mc; ++m) g = fmaf(attn[r][m], Hs[r][m][j], g);
            gs[r][j] = g;
        }
        __syncthreads();

        // --- rs = g @ Wv + bv ;  h = sigmoid(q + rs)
        float ra0 = bv[j], ra1 = ra0;
        #pragma unroll 8
        for (int d = 0; d < Dc; ++d) {
            const float w = Wv[d * Dc + j];
            ra0 = fmaf(gs[0][d], w, ra0);
            ra1 = fmaf(gs[1][d], w, ra1);
        }
        const float h0 = sigf(qa0 + ra0);
        const float h1 = sigf(qa1 + ra1);
        hsh[0][j] = h0; hsh[1][j] = h1;
        oh[(b0 + 0) * Dc + j] = h0;
        oh[(b0 + 1) * Dc + j] = h1;
        ohist[((long long)(b0 + 0) * Tc + cur) * Dc + j] = h0;
        ohist[((long long)(b0 + 1) * Tc + cur) * Dc + j] = h1;
        __syncthreads();

        // --- y = sigmoid(h @ Wb + bb + h)
        float ya0 = bb[j] + h0, ya1 = bb[j] + h1;
        #pragma unroll 8
        for (int d = 0; d < Dc; ++d) {
            const float w = Wb[d * Dc + j];
            ya0 = fmaf(hsh[0][d], w, ya0);
            ya1 = fmaf(hsh[1][d], w, ya1);
        }
        oy[(b0 + 0) * Dc + j] = sigf(ya0);
        oy[(b0 + 1) * Dc + j] = sigf(ya1);
    }

    // ================= copy phase: ALL blocks grid-stride the history =======
    {
        const float4* __restrict__ src = reinterpret_cast<const float4*>(hist);
        float4*       __restrict__ dst = reinterpret_cast<float4*>(ohist);
        const long long total  = (long long)Bc * Tc * (Dc / 4);   // 64M float4
        const long long stride = (long long)GRID * 256;
        long long i = (long long)blockIdx.x * 256 + j;
        for (; i + 3 * stride < total; i += 4 * stride) {
            const long long i0 = i, i1 = i + stride, i2 = i + 2 * stride,
                            i3 = i + 3 * stride;
            const float4 v0 = __ldcs(src + i0);
            const float4 v1 = __ldcs(src + i1);
            const float4 v2 = __ldcs(src + i2);
            const float4 v3 = __ldcs(src + i3);
            if ((int)((i0 >> 6) & (Tc - 1)) != cur) __stcs(dst + i0, v0);
            if ((int)((i1 >> 6) & (Tc - 1)) != cur) __stcs(dst + i1, v1);
            if ((int)((i2 >> 6) & (Tc - 1)) != cur) __stcs(dst + i2, v2);
            if ((int)((i3 >> 6) & (Tc - 1)) != cur) __stcs(dst + i3, v3);
        }
        for (; i < total; i += stride) {
            const float4 v = __ldcs(src + i);
            if ((int)((i >> 6) & (Tc - 1)) != cur) __stcs(dst + i, v);
        }
    }
}

} // namespace

extern "C" void kernel_launch(void* const* d_in, const int* in_sizes, int n_in,
                              void* d_out, int out_size)
{
    const float* x    = (const float*)d_in[0];
    const float* hist = (const float*)d_in[1];
    const float* Wi   = (const float*)d_in[2];
    const float* bi   = (const float*)d_in[3];
    const float* Wk   = (const float*)d_in[4];
    const float* bk   = (const float*)d_in[5];
    const float* Wv   = (const float*)d_in[6];
    const float* bv   = (const float*)d_in[7];
    const float* Wb   = (const float*)d_in[8];
    const float* bb   = (const float*)d_in[9];
    const int*   jp   = (const int*)d_in[10];
    const int*   cur  = (const int*)d_in[11];

    float* out   = (float*)d_out;
    float* oh    = out;                    // h:  [B, D]
    float* oy    = out + Bc * Dc;          // y:  [B, D]
    float* ohist = out + 2 * Bc * Dc;      // new_history: [B, T, D]

    (void)in_sizes; (void)n_in; (void)out_size;

    bjrnn_fused<<<GRID, 256>>>(
        x, hist, Wi, bi, Wk, bk, Wv, bv, Wb, bb, jp, cur, oh, oy, ohist);
}